// round 14
// baseline (speedup 1.0000x reference)
#include <cuda_runtime.h>
#include <cuda_bf16.h>
#include <math.h>

#define T_STEPS 64
#define BATCH   32
#define NINP    1024
#define S1D     1024
#define R1D     1024
#define S2D     1024
#define R2D     1024
#define HID     2048
#define VOCAB   32000
#define ROWS    (T_STEPS*BATCH)
#define DECAYF  0.6f
#define THRESHF 0.6f

// Scratch (device globals; no runtime allocation allowed)
__device__ float g_E [ROWS*NINP];
__device__ float g_C1[ROWS*S1D];
__device__ float g_U1[ROWS*R1D];
__device__ float g_O1[ROWS*HID];
__device__ float g_A2[ROWS*S2D];
__device__ float g_U2[ROWS*R2D];
__device__ float g_O2[ROWS*HID];
__device__ unsigned g_At[ROWS*HID];          // O2 as tf32 bits (16 MB)
__device__ unsigned g_Wt[VOCAB*HID];         // dec_w as tf32 bits (262 MB)

// ---------------------------------------------------------------------------
// XLA fast-tanh with aarch64 LLVM FMA contraction (r12 PASSING recipe —
// FROZEN). logistic = fma(0.5, tanh(0.5x), 0.5).
// ---------------------------------------------------------------------------
__device__ __forceinline__ float xla_tanh(float x) {
    const float a1  =  4.89352455891786e-03f;
    const float a3  =  6.37261928875436e-04f;
    const float a5  =  1.48572235717979e-05f;
    const float a7  =  5.12229709037114e-08f;
    const float a9  = -8.60467152213735e-11f;
    const float a11 =  2.00018790482477e-13f;
    const float a13 = -2.76076847742355e-16f;
    const float b0  =  4.89352518554385e-03f;
    const float b2  =  2.26843463243900e-03f;
    const float b4  =  1.18534705686654e-04f;
    const float b6  =  1.19825839466702e-06f;
    float xc = fminf(fmaxf(x, -9.0f), 9.0f);
    float x2 = __fmul_rn(xc, xc);
    float p  = __fmaf_rn(x2, a13, a11);
    p = __fmaf_rn(x2, p, a9);
    p = __fmaf_rn(x2, p, a7);
    p = __fmaf_rn(x2, p, a5);
    p = __fmaf_rn(x2, p, a3);
    p = __fmaf_rn(x2, p, a1);
    float num = __fmul_rn(xc, p);
    float q   = __fmaf_rn(x2, b6, b4);
    q = __fmaf_rn(x2, q, b2);
    q = __fmaf_rn(x2, q, b0);
    float t = __fdiv_rn(num, q);
    return (fabsf(x) < 0.0004f) ? x : t;
}

__device__ __forceinline__ float xla_sigmoid(float z) {
    float t = xla_tanh(__fmul_rn(0.5f, z));
    return __fmaf_rn(0.5f, t, 0.5f);
}

__device__ __forceinline__ unsigned f2tf32(float x) {
    unsigned r;
    asm("cvt.rna.tf32.f32 %0, %1;" : "=r"(r) : "f"(x));
    return r;
}

// Embedding gather
__global__ void k_gather(const int* __restrict__ idx,
                         const float* __restrict__ enc,
                         float* __restrict__ E)
{
    int row = blockIdx.x;
    int tok = idx[row];
    const float4* src = (const float4*)(enc + (size_t)tok * NINP);
    float4*       dst = (float4*)(E + (size_t)row * NINP);
    for (int i = threadIdx.x; i < NINP/4; i += blockDim.x) dst[i] = src[i];
}

// f32 -> tf32-bit conversion (grid-stride, float4)
__global__ void k_cvt(const float* __restrict__ s, unsigned* __restrict__ d, int n4)
{
    int i = blockIdx.x * blockDim.x + threadIdx.x;
    int stride = gridDim.x * blockDim.x;
    for (; i < n4; i += stride) {
        float4 v = *(const float4*)(s + (size_t)i * 4);
        uint4 r;
        r.x = f2tf32(v.x); r.y = f2tf32(v.y);
        r.z = f2tf32(v.z); r.w = f2tf32(v.w);
        *(uint4*)(d + (size_t)i * 4) = r;
    }
}

// ---------------------------------------------------------------------------
// Tiled fp32 SGEMM (NN), spike path — FROZEN numerics (monolithic ascending
// __fmaf_rn chain; ACC=true folds second kc=1024 panel with one __fadd_rn).
// ---------------------------------------------------------------------------
template<bool ACC>
__global__ void sgemm_nn(int M, int N, int K,
                         const float* __restrict__ A, int lda,
                         const float* __restrict__ B, int ldb,
                         float* __restrict__ C, int ldc)
{
    const int BK = 16;
    __shared__ float As[16][132];
    __shared__ float Bs[16][132];

    int tid = threadIdx.x;
    int tx  = tid & 15;
    int ty  = tid >> 4;
    int m0  = blockIdx.y * 128;
    int n0  = blockIdx.x * 128;

    float acc[8][8];
#pragma unroll
    for (int i = 0; i < 8; i++)
#pragma unroll
        for (int j = 0; j < 8; j++) acc[i][j] = 0.f;

    int a_r = tid >> 2;
    int a_k = (tid & 3) * 4;

    for (int kt = 0; kt < K; kt += BK) {
#pragma unroll
        for (int L = 0; L < 2; L++) {
            int m = a_r + L * 64;
            float4 v = *(const float4*)(A + (size_t)(m0 + m) * lda + kt + a_k);
            As[a_k + 0][m] = v.x;
            As[a_k + 1][m] = v.y;
            As[a_k + 2][m] = v.z;
            As[a_k + 3][m] = v.w;
        }
#pragma unroll
        for (int L = 0; L < 2; L++) {
            int k = (tid >> 5) + L * 8;
            int n = (tid & 31) * 4;
            float4 v = *(const float4*)(B + (size_t)(kt + k) * ldb + n0 + n);
            *(float4*)(&Bs[k][n]) = v;
        }
        __syncthreads();

#pragma unroll
        for (int k = 0; k < BK; k++) {
            float a[8], b[8];
            *(float4*)(a)     = *(const float4*)(&As[k][ty * 8]);
            *(float4*)(a + 4) = *(const float4*)(&As[k][ty * 8 + 4]);
            *(float4*)(b)     = *(const float4*)(&Bs[k][tx * 8]);
            *(float4*)(b + 4) = *(const float4*)(&Bs[k][tx * 8 + 4]);
#pragma unroll
            for (int i = 0; i < 8; i++)
#pragma unroll
                for (int j = 0; j < 8; j++)
                    acc[i][j] = __fmaf_rn(a[i], b[j], acc[i][j]);
        }
        __syncthreads();
    }

#pragma unroll
    for (int i = 0; i < 8; i++) {
        int m = m0 + ty * 8 + i;
        float* crow = C + (size_t)m * ldc + n0 + tx * 8;
        if (ACC) {
#pragma unroll
            for (int j = 0; j < 8; j++) crow[j] = __fadd_rn(crow[j], acc[i][j]);
        } else {
#pragma unroll
            for (int j = 0; j < 8; j++) crow[j] = acc[i][j];
        }
    }
}

// ---------------------------------------------------------------------------
// TF32 decoder v2: pre-converted tf32 inputs, cp.async double-buffered,
// grid = (m-tiles fast, n-tiles slow) for dec_w single-pass DRAM traffic.
// C[M,N] = A[M,K]*B[N,K]^T + bias; fragment layout identical to r13 (PASSED).
// ---------------------------------------------------------------------------
__global__ __launch_bounds__(256) void tf32_dec2(
    const unsigned* __restrict__ At,   // [ROWS, HID] tf32 bits
    const unsigned* __restrict__ Wt,   // [VOCAB, HID] tf32 bits
    const float* __restrict__ bias,
    float* __restrict__ C)
{
    extern __shared__ unsigned sm[];
    unsigned (*As)[128][36] = (unsigned (*)[128][36])(sm);
    unsigned (*Bs)[128][36] = (unsigned (*)[128][36])(sm + 2 * 128 * 36);

    int tid  = threadIdx.x;
    int wid  = tid >> 5;
    int lane = tid & 31;
    int gid  = lane >> 2;
    int tig  = lane & 3;
    int wm   = wid >> 2;
    int wn   = wid & 3;

    int m0 = blockIdx.x * 128;     // m fast -> 16 m-tiles share each W n-tile
    int n0 = blockIdx.y * 128;

    float c[4][4][4];
#pragma unroll
    for (int mf = 0; mf < 4; mf++)
#pragma unroll
        for (int nf = 0; nf < 4; nf++)
#pragma unroll
            for (int q = 0; q < 4; q++) c[mf][nf][q] = 0.f;

    // stage loader: 128 rows x 32 u32 per array = 1024 16B-chunks / array
#define DEC_ISSUE(s, kt)                                                      \
    {                                                                         \
        _Pragma("unroll")                                                     \
        for (int i = 0; i < 4; i++) {                                         \
            int ch  = tid + i * 256;                                          \
            int row = ch >> 3;                                                \
            int q   = (ch & 7) * 4;                                           \
            unsigned da = (unsigned)__cvta_generic_to_shared(&As[s][row][q]); \
            asm volatile("cp.async.ca.shared.global [%0], [%1], 16;\n"        \
                         :: "r"(da),                                          \
                            "l"(At + (size_t)(m0 + row) * HID + (kt) + q));   \
            unsigned db = (unsigned)__cvta_generic_to_shared(&Bs[s][row][q]); \
            asm volatile("cp.async.ca.shared.global [%0], [%1], 16;\n"        \
                         :: "r"(db),                                          \
                            "l"(Wt + (size_t)(n0 + row) * HID + (kt) + q));   \
        }                                                                     \
        asm volatile("cp.async.commit_group;\n" ::);                          \
    }

    DEC_ISSUE(0, 0);

    for (int it = 0; it < HID / 32; it++) {
        int s = it & 1;
        if (it < HID / 32 - 1) {
            DEC_ISSUE(s ^ 1, (it + 1) * 32);
        } else {
            asm volatile("cp.async.commit_group;\n" ::);   // empty group
        }
        asm volatile("cp.async.wait_group 1;\n" ::);
        __syncthreads();

#pragma unroll
        for (int ks = 0; ks < 4; ks++) {
            int k0 = ks * 8;
            unsigned a[4][4], b[4][2];
#pragma unroll
            for (int mf = 0; mf < 4; mf++) {
                int r = wm * 64 + mf * 16 + gid;
                a[mf][0] = As[s][r    ][k0 + tig];
                a[mf][1] = As[s][r + 8][k0 + tig];
                a[mf][2] = As[s][r    ][k0 + tig + 4];
                a[mf][3] = As[s][r + 8][k0 + tig + 4];
            }
#pragma unroll
            for (int nf = 0; nf < 4; nf++) {
                int cn = wn * 32 + nf * 8 + gid;
                b[nf][0] = Bs[s][cn][k0 + tig];
                b[nf][1] = Bs[s][cn][k0 + tig + 4];
            }
#pragma unroll
            for (int mf = 0; mf < 4; mf++)
#pragma unroll
                for (int nf = 0; nf < 4; nf++)
                    asm volatile(
                        "mma.sync.aligned.m16n8k8.row.col.f32.tf32.tf32.f32 "
                        "{%0,%1,%2,%3}, {%4,%5,%6,%7}, {%8,%9}, {%0,%1,%2,%3};"
                        : "+f"(c[mf][nf][0]), "+f"(c[mf][nf][1]),
                          "+f"(c[mf][nf][2]), "+f"(c[mf][nf][3])
                        : "r"(a[mf][0]), "r"(a[mf][1]), "r"(a[mf][2]), "r"(a[mf][3]),
                          "r"(b[nf][0]), "r"(b[nf][1]));
        }
        __syncthreads();
    }

#pragma unroll
    for (int mf = 0; mf < 4; mf++) {
        int r = m0 + wm * 64 + mf * 16 + gid;
#pragma unroll
        for (int nf = 0; nf < 4; nf++) {
            int cn = n0 + wn * 32 + nf * 8 + 2 * tig;
            float b0v = bias[cn], b1v = bias[cn + 1];
            C[(size_t)r * VOCAB + cn]           = c[mf][nf][0] + b0v;
            C[(size_t)r * VOCAB + cn + 1]       = c[mf][nf][1] + b1v;
            C[(size_t)(r + 8) * VOCAB + cn]     = c[mf][nf][2] + b0v;
            C[(size_t)(r + 8) * VOCAB + cn + 1] = c[mf][nf][3] + b1v;
        }
    }
#undef DEC_ISSUE
}

// ---------------------------------------------------------------------------
// LIF membrane/spike scan — FROZEN (contracted fmla form).
// ---------------------------------------------------------------------------
__global__ void k_spike(const float* __restrict__ Cm, float* __restrict__ O)
{
    int gid = blockIdx.x * blockDim.x + threadIdx.x;
    int b = gid >> 10;
    int s = gid & 1023;
    float mem = 0.f, spk = 0.f;
    for (int t = 0; t < T_STEPS; t++) {
        float c = Cm[((size_t)(t * BATCH + b) << 10) + s];
        float m1 = __fmul_rn(mem, __fsub_rn(1.f, spk));
        mem = __fmaf_rn(m1, DECAYF, c);
        spk = (__fsub_rn(mem, THRESHF) > 0.f) ? 1.f : 0.f;
        O[((size_t)(t * BATCH + b) << 11) + s] = spk;
    }
}

// ---------------------------------------------------------------------------
// Recurrent step v2 — identical per-element chain to r12/13 (FROZEN numerics)
// but W read via uniform global float4 loads (warp-broadcast, L2-resident)
// instead of an smem tile: drops the LDS bottleneck.
// ---------------------------------------------------------------------------
__global__ void k_rnn_step(const float* __restrict__ U,
                           const float* __restrict__ Xp, int xstride,
                           const float* __restrict__ W,
                           float* __restrict__ Y)
{
    __shared__ float sx[32 * 33];

    int tid = threadIdx.x;          // 0..127
    int b   = tid & 31;
    int jg  = tid >> 5;             // 0..3
    int j0  = blockIdx.x * 16 + jg * 4;

    float acc[4] = {0.f, 0.f, 0.f, 0.f};

    for (int kc = 0; kc < 1024; kc += 32) {
#pragma unroll
        for (int p = 0; p < 8; p++) {
            int e  = tid + p * 128;
            int bl = e >> 5;
            int kl = e & 31;
            sx[kl * 33 + bl] = Xp[(size_t)bl * xstride + kc + kl];
        }
        __syncthreads();
#pragma unroll
        for (int k = 0; k < 32; k++) {
            float  xv = sx[k * 33 + b];
            float4 wv = *(const float4*)(W + (size_t)(kc + k) * 1024 + j0);
            acc[0] = __fmaf_rn(xv, wv.x, acc[0]);
            acc[1] = __fmaf_rn(xv, wv.y, acc[1]);
            acc[2] = __fmaf_rn(xv, wv.z, acc[2]);
            acc[3] = __fmaf_rn(xv, wv.w, acc[3]);
        }
        __syncthreads();
    }

#pragma unroll
    for (int j = 0; j < 4; j++) {
        float z = __fadd_rn(U[(size_t)b * 1024 + j0 + j], acc[j]);
        Y[(size_t)b * HID + j0 + j] = xla_sigmoid(z);
    }
}

// Copy final h1_y / h2_y states into the tail of d_out.
__global__ void k_tail(const float* __restrict__ O1,
                       const float* __restrict__ O2,
                       float* __restrict__ out)
{
    int gid  = blockIdx.x * blockDim.x + threadIdx.x;
    int half = gid >> 15;
    int i    = gid & 32767;
    int b    = i >> 10;
    int r    = i & 1023;
    const float* src = (half == 0) ? O1 : O2;
    out[(size_t)T_STEPS * BATCH * VOCAB + (size_t)half * 32768 + i] =
        src[(size_t)((T_STEPS - 1) * BATCH + b) * HID + 1024 + r];
}

extern "C" void kernel_launch(void* const* d_in, const int* in_sizes, int n_in,
                              void* d_out, int out_size)
{
    const int*   raw     = (const int*)  d_in[0];
    const float* h1y0    = (const float*)d_in[1];
    const float* h2y0    = (const float*)d_in[2];
    const float* enc     = (const float*)d_in[3];
    const float* snn_fc1 = (const float*)d_in[4];
    const float* snn_fc2 = (const float*)d_in[5];
    const float* rnn_fc1 = (const float*)d_in[6];
    const float* rnn_fc2 = (const float*)d_in[7];
    const float* rnn_fv1 = (const float*)d_in[8];
    const float* rnn_fv2 = (const float*)d_in[9];
    const float* dec_w   = (const float*)d_in[10];
    const float* dec_b   = (const float*)d_in[11];
    float* out = (float*)d_out;

    float *E, *C1, *U1, *O1, *A2, *U2, *O2;
    unsigned *At, *Wt;
    cudaGetSymbolAddress((void**)&E,  g_E);
    cudaGetSymbolAddress((void**)&C1, g_C1);
    cudaGetSymbolAddress((void**)&U1, g_U1);
    cudaGetSymbolAddress((void**)&O1, g_O1);
    cudaGetSymbolAddress((void**)&A2, g_A2);
    cudaGetSymbolAddress((void**)&U2, g_U2);
    cudaGetSymbolAddress((void**)&O2, g_O2);
    cudaGetSymbolAddress((void**)&At, g_At);
    cudaGetSymbolAddress((void**)&Wt, g_Wt);

    cudaFuncSetAttribute(tf32_dec2,
                         cudaFuncAttributeMaxDynamicSharedMemorySize, 73728);

    // 0) pre-convert decoder weights to tf32 bits (input-only, one pass)
    k_cvt<<<2048, 256>>>(dec_w, Wt, VOCAB * HID / 4);

    // 1) gather embeddings
    k_gather<<<ROWS, 256>>>(raw, enc, E);

    // 2) input projections (K=1024 single kc panel -> monolithic chain)
    dim3 g1(S1D / 128, ROWS / 128);
    sgemm_nn<false><<<g1, 256>>>(ROWS, S1D, NINP, E, NINP, snn_fc1, S1D, C1, S1D);
    sgemm_nn<false><<<g1, 256>>>(ROWS, R1D, NINP, E, NINP, rnn_fc1, R1D, U1, R1D);

    // 3) layer-1 spike scan
    k_spike<<<128, 256>>>(C1, O1);

    // 4) layer-1 recurrent sigmoid chain
    for (int t = 0; t < T_STEPS; t++) {
        const float* xp = (t == 0) ? h1y0 : (O1 + (size_t)(t - 1) * BATCH * HID + 1024);
        int xs = (t == 0) ? 1024 : HID;
        k_rnn_step<<<64, 128>>>(U1 + (size_t)t * BATCH * 1024, xp, xs, rnn_fv1,
                                O1 + (size_t)t * BATCH * HID + 1024);
    }

    // 5) layer-2 projections: kc=1024 panel fold via store + accumulate
    sgemm_nn<false><<<g1, 256>>>(ROWS, S2D, 1024, O1, HID, snn_fc2, S2D, A2, S2D);
    sgemm_nn<true ><<<g1, 256>>>(ROWS, S2D, 1024, O1 + 1024, HID,
                                 snn_fc2 + (size_t)1024 * S2D, S2D, A2, S2D);
    sgemm_nn<false><<<g1, 256>>>(ROWS, R2D, 1024, O1, HID, rnn_fc2, R2D, U2, R2D);
    sgemm_nn<true ><<<g1, 256>>>(ROWS, R2D, 1024, O1 + 1024, HID,
                                 rnn_fc2 + (size_t)1024 * R2D, R2D, U2, R2D);

    // 6) layer-2 spike scan
    k_spike<<<128, 256>>>(A2, O2);

    // 7) layer-2 recurrent sigmoid chain
    for (int t = 0; t < T_STEPS; t++) {
        const float* xp = (t == 0) ? h2y0 : (O2 + (size_t)(t - 1) * BATCH * HID + 1024);
        int xs = (t == 0) ? 1024 : HID;
        k_rnn_step<<<64, 128>>>(U2 + (size_t)t * BATCH * 1024, xp, xs, rnn_fv2,
                                O2 + (size_t)t * BATCH * HID + 1024);
    }

    // 8) decoder: convert O2 to tf32 bits, then pipelined TF32 GEMM
    k_cvt<<<512, 256>>>(O2, At, ROWS * HID / 4);
    dim3 gd(ROWS / 128, VOCAB / 128);   // (16, 250): m fast, n slow
    tf32_dec2<<<gd, 256, 73728>>>(At, Wt, dec_b, out);

    // 9) final recurrent states into output tail
    k_tail<<<256, 256>>>(O1, O2, out);
}

// round 15
// speedup vs baseline: 1.0968x; 1.0968x over previous
#include <cuda_runtime.h>
#include <cuda_bf16.h>
#include <math.h>

#define T_STEPS 64
#define BATCH   32
#define NINP    1024
#define HID     2048
#define VOCAB   32000
#define ROWS    (T_STEPS*BATCH)
#define DECAYF  0.6f
#define THRESHF 0.6f

// Scratch (device globals; no runtime allocation allowed)
__device__ float g_E  [ROWS*NINP];      //  8 MB gathered embeddings
__device__ float g_CU1[ROWS*HID];       // 16 MB [C1 | U1] fused
__device__ float g_O1 [ROWS*HID];       // 16 MB [spike1 | h1_y]
__device__ float g_AU2[ROWS*HID];       // 16 MB [A2 | U2] fused
__device__ float g_O2 [ROWS*HID];       // 16 MB [spike2 | h2_y]
__device__ float g_W1f[NINP*HID];       //  8 MB [snn_fc1 | rnn_fc1]
__device__ float g_W2f[HID*HID];        // 16 MB [snn_fc2 | rnn_fc2]

// ---------------------------------------------------------------------------
// XLA fast-tanh with aarch64 LLVM FMA contraction (r12 recipe — FROZEN).
// ---------------------------------------------------------------------------
__device__ __forceinline__ float xla_tanh(float x) {
    const float a1  =  4.89352455891786e-03f;
    const float a3  =  6.37261928875436e-04f;
    const float a5  =  1.48572235717979e-05f;
    const float a7  =  5.12229709037114e-08f;
    const float a9  = -8.60467152213735e-11f;
    const float a11 =  2.00018790482477e-13f;
    const float a13 = -2.76076847742355e-16f;
    const float b0  =  4.89352518554385e-03f;
    const float b2  =  2.26843463243900e-03f;
    const float b4  =  1.18534705686654e-04f;
    const float b6  =  1.19825839466702e-06f;
    float xc = fminf(fmaxf(x, -9.0f), 9.0f);
    float x2 = __fmul_rn(xc, xc);
    float p  = __fmaf_rn(x2, a13, a11);
    p = __fmaf_rn(x2, p, a9);
    p = __fmaf_rn(x2, p, a7);
    p = __fmaf_rn(x2, p, a5);
    p = __fmaf_rn(x2, p, a3);
    p = __fmaf_rn(x2, p, a1);
    float num = __fmul_rn(xc, p);
    float q   = __fmaf_rn(x2, b6, b4);
    q = __fmaf_rn(x2, q, b2);
    q = __fmaf_rn(x2, q, b0);
    float t = __fdiv_rn(num, q);
    return (fabsf(x) < 0.0004f) ? x : t;
}

__device__ __forceinline__ float xla_sigmoid(float z) {
    float t = xla_tanh(__fmul_rn(0.5f, z));
    return __fmaf_rn(0.5f, t, 0.5f);
}

__device__ __forceinline__ unsigned f2tf32(float x) {
    unsigned r;
    asm("cvt.rna.tf32.f32 %0, %1;" : "=r"(r) : "f"(x));
    return r;
}

// Embedding gather
__global__ void k_gather(const int* __restrict__ idx,
                         const float* __restrict__ enc,
                         float* __restrict__ E)
{
    int row = blockIdx.x;
    int tok = idx[row];
    const float4* src = (const float4*)(enc + (size_t)tok * NINP);
    float4*       dst = (float4*)(E + (size_t)row * NINP);
    for (int i = threadIdx.x; i < NINP/4; i += blockDim.x) dst[i] = src[i];
}

// Fuse two [K,1024] weight matrices side-by-side into [K,2048]
__global__ void k_fusew(const float* __restrict__ A, const float* __restrict__ B,
                        float* __restrict__ D, int K)
{
    int i = blockIdx.x * blockDim.x + threadIdx.x;
    int n4 = K * 256;                       // float4s per half
    int stride = gridDim.x * blockDim.x;
    for (; i < n4; i += stride) {
        int row  = i >> 8;
        int col4 = (i & 255) * 4;
        *(float4*)(D + (size_t)row * HID + col4) =
            *(const float4*)(A + (size_t)row * 1024 + col4);
        *(float4*)(D + (size_t)row * HID + 1024 + col4) =
            *(const float4*)(B + (size_t)row * 1024 + col4);
    }
}

// ---------------------------------------------------------------------------
// Tiled fp32 SGEMM (NN), spike path — FROZEN per-element numerics
// (monolithic ascending __fmaf_rn chain; ACC folds the second kc=1024 panel
// with one __fadd_rn). BM=BN=128, BK=16, 256 threads, 8x8 microtile.
// ---------------------------------------------------------------------------
template<bool ACC>
__global__ void sgemm_nn(int M, int N, int K,
                         const float* __restrict__ A, int lda,
                         const float* __restrict__ B, int ldb,
                         float* __restrict__ C, int ldc)
{
    const int BK = 16;
    __shared__ float As[16][132];
    __shared__ float Bs[16][132];

    int tid = threadIdx.x;
    int tx  = tid & 15;
    int ty  = tid >> 4;
    int m0  = blockIdx.y * 128;
    int n0  = blockIdx.x * 128;

    float acc[8][8];
#pragma unroll
    for (int i = 0; i < 8; i++)
#pragma unroll
        for (int j = 0; j < 8; j++) acc[i][j] = 0.f;

    int a_r = tid >> 2;
    int a_k = (tid & 3) * 4;

    for (int kt = 0; kt < K; kt += BK) {
#pragma unroll
        for (int L = 0; L < 2; L++) {
            int m = a_r + L * 64;
            float4 v = *(const float4*)(A + (size_t)(m0 + m) * lda + kt + a_k);
            As[a_k + 0][m] = v.x;
            As[a_k + 1][m] = v.y;
            As[a_k + 2][m] = v.z;
            As[a_k + 3][m] = v.w;
        }
#pragma unroll
        for (int L = 0; L < 2; L++) {
            int k = (tid >> 5) + L * 8;
            int n = (tid & 31) * 4;
            float4 v = *(const float4*)(B + (size_t)(kt + k) * ldb + n0 + n);
            *(float4*)(&Bs[k][n]) = v;
        }
        __syncthreads();

#pragma unroll
        for (int k = 0; k < BK; k++) {
            float a[8], b[8];
            *(float4*)(a)     = *(const float4*)(&As[k][ty * 8]);
            *(float4*)(a + 4) = *(const float4*)(&As[k][ty * 8 + 4]);
            *(float4*)(b)     = *(const float4*)(&Bs[k][tx * 8]);
            *(float4*)(b + 4) = *(const float4*)(&Bs[k][tx * 8 + 4]);
#pragma unroll
            for (int i = 0; i < 8; i++)
#pragma unroll
                for (int j = 0; j < 8; j++)
                    acc[i][j] = __fmaf_rn(a[i], b[j], acc[i][j]);
        }
        __syncthreads();
    }

#pragma unroll
    for (int i = 0; i < 8; i++) {
        int m = m0 + ty * 8 + i;
        float* crow = C + (size_t)m * ldc + n0 + tx * 8;
        if (ACC) {
#pragma unroll
            for (int j = 0; j < 8; j++) crow[j] = __fadd_rn(crow[j], acc[i][j]);
        } else {
#pragma unroll
            for (int j = 0; j < 8; j++) crow[j] = acc[i][j];
        }
    }
}

// ---------------------------------------------------------------------------
// TF32 tensor-core decoder — r13 version VERBATIM (known 2.9 ms, PASSED).
// C[M,N] = A[M,K] * B[N,K]^T + bias.  M=2048, N=32000, K=2048.
// ---------------------------------------------------------------------------
__global__ __launch_bounds__(256) void tf32_dec(
    const float* __restrict__ A,
    const float* __restrict__ B,
    const float* __restrict__ bias,
    float* __restrict__ C)
{
    __shared__ unsigned As[128][36];
    __shared__ unsigned Bs[128][36];

    int tid  = threadIdx.x;
    int wid  = tid >> 5;
    int lane = tid & 31;
    int gid  = lane >> 2;
    int tig  = lane & 3;
    int wm   = wid >> 2;
    int wn   = wid & 3;

    int m0 = blockIdx.y * 128;
    int n0 = blockIdx.x * 128;

    float c[4][4][4];
#pragma unroll
    for (int mf = 0; mf < 4; mf++)
#pragma unroll
        for (int nf = 0; nf < 4; nf++)
#pragma unroll
            for (int q = 0; q < 4; q++) c[mf][nf][q] = 0.f;

    int lr = tid >> 3;
    int lk = (tid & 7) * 4;

    for (int kt = 0; kt < HID; kt += 32) {
#pragma unroll
        for (int i = 0; i < 4; i++) {
            int row = lr + i * 32;
            float4 v = *(const float4*)(A + (size_t)(m0 + row) * HID + kt + lk);
            As[row][lk + 0] = f2tf32(v.x);
            As[row][lk + 1] = f2tf32(v.y);
            As[row][lk + 2] = f2tf32(v.z);
            As[row][lk + 3] = f2tf32(v.w);
        }
#pragma unroll
        for (int i = 0; i < 4; i++) {
            int row = lr + i * 32;
            float4 v = *(const float4*)(B + (size_t)(n0 + row) * HID + kt + lk);
            Bs[row][lk + 0] = f2tf32(v.x);
            Bs[row][lk + 1] = f2tf32(v.y);
            Bs[row][lk + 2] = f2tf32(v.z);
            Bs[row][lk + 3] = f2tf32(v.w);
        }
        __syncthreads();

#pragma unroll
        for (int ks = 0; ks < 4; ks++) {
            int k0 = ks * 8;
            unsigned a[4][4], b[4][2];
#pragma unroll
            for (int mf = 0; mf < 4; mf++) {
                int r = wm * 64 + mf * 16 + gid;
                a[mf][0] = As[r    ][k0 + tig];
                a[mf][1] = As[r + 8][k0 + tig];
                a[mf][2] = As[r    ][k0 + tig + 4];
                a[mf][3] = As[r + 8][k0 + tig + 4];
            }
#pragma unroll
            for (int nf = 0; nf < 4; nf++) {
                int cn = wn * 32 + nf * 8 + gid;
                b[nf][0] = Bs[cn][k0 + tig];
                b[nf][1] = Bs[cn][k0 + tig + 4];
            }
#pragma unroll
            for (int mf = 0; mf < 4; mf++)
#pragma unroll
                for (int nf = 0; nf < 4; nf++)
                    asm volatile(
                        "mma.sync.aligned.m16n8k8.row.col.f32.tf32.tf32.f32 "
                        "{%0,%1,%2,%3}, {%4,%5,%6,%7}, {%8,%9}, {%0,%1,%2,%3};"
                        : "+f"(c[mf][nf][0]), "+f"(c[mf][nf][1]),
                          "+f"(c[mf][nf][2]), "+f"(c[mf][nf][3])
                        : "r"(a[mf][0]), "r"(a[mf][1]), "r"(a[mf][2]), "r"(a[mf][3]),
                          "r"(b[nf][0]), "r"(b[nf][1]));
        }
        __syncthreads();
    }

#pragma unroll
    for (int mf = 0; mf < 4; mf++) {
        int r = m0 + wm * 64 + mf * 16 + gid;
#pragma unroll
        for (int nf = 0; nf < 4; nf++) {
            int cn = n0 + wn * 32 + nf * 8 + 2 * tig;
            float b0v = bias[cn], b1v = bias[cn + 1];
            C[(size_t)r * VOCAB + cn]           = c[mf][nf][0] + b0v;
            C[(size_t)r * VOCAB + cn + 1]       = c[mf][nf][1] + b1v;
            C[(size_t)(r + 8) * VOCAB + cn]     = c[mf][nf][2] + b0v;
            C[(size_t)(r + 8) * VOCAB + cn + 1] = c[mf][nf][3] + b1v;
        }
    }
}

// ---------------------------------------------------------------------------
// LIF membrane/spike scan — FROZEN arithmetic; Cm row stride parameterized
// (fused [C|U] buffers have stride 2048).
// ---------------------------------------------------------------------------
__global__ void k_spike(const float* __restrict__ Cm, int cstride,
                        float* __restrict__ O)
{
    int gid = blockIdx.x * blockDim.x + threadIdx.x;
    int b = gid >> 10;
    int s = gid & 1023;
    float mem = 0.f, spk = 0.f;
    for (int t = 0; t < T_STEPS; t++) {
        float c = Cm[(size_t)(t * BATCH + b) * cstride + s];
        float m1 = __fmul_rn(mem, __fsub_rn(1.f, spk));
        mem = __fmaf_rn(m1, DECAYF, c);
        spk = (__fsub_rn(mem, THRESHF) > 0.f) ? 1.f : 0.f;
        O[((size_t)(t * BATCH + b) << 11) + s] = spk;
    }
}

// ---------------------------------------------------------------------------
// Recurrent step — FROZEN per-element chain; W via uniform global float4
// loads (warp-broadcast, r14-verified bit-identical). U row stride param.
// ---------------------------------------------------------------------------
__global__ void k_rnn_step(const float* __restrict__ U, int ustride,
                           const float* __restrict__ Xp, int xstride,
                           const float* __restrict__ W,
                           float* __restrict__ Y)
{
    __shared__ float sx[32 * 33];

    int tid = threadIdx.x;          // 0..127
    int b   = tid & 31;
    int jg  = tid >> 5;             // 0..3
    int j0  = blockIdx.x * 16 + jg * 4;

    float acc[4] = {0.f, 0.f, 0.f, 0.f};

    for (int kc = 0; kc < 1024; kc += 32) {
#pragma unroll
        for (int p = 0; p < 8; p++) {
            int e  = tid + p * 128;
            int bl = e >> 5;
            int kl = e & 31;
            sx[kl * 33 + bl] = Xp[(size_t)bl * xstride + kc + kl];
        }
        __syncthreads();
#pragma unroll
        for (int k = 0; k < 32; k++) {
            float  xv = sx[k * 33 + b];
            float4 wv = *(const float4*)(W + (size_t)(kc + k) * 1024 + j0);
            acc[0] = __fmaf_rn(xv, wv.x, acc[0]);
            acc[1] = __fmaf_rn(xv, wv.y, acc[1]);
            acc[2] = __fmaf_rn(xv, wv.z, acc[2]);
            acc[3] = __fmaf_rn(xv, wv.w, acc[3]);
        }
        __syncthreads();
    }

#pragma unroll
    for (int j = 0; j < 4; j++) {
        float z = __fadd_rn(U[(size_t)b * ustride + j0 + j], acc[j]);
        Y[(size_t)b * HID + j0 + j] = xla_sigmoid(z);
    }
}

// Copy final h1_y / h2_y states into the tail of d_out.
__global__ void k_tail(const float* __restrict__ O1,
                       const float* __restrict__ O2,
                       float* __restrict__ out)
{
    int gid  = blockIdx.x * blockDim.x + threadIdx.x;
    int half = gid >> 15;
    int i    = gid & 32767;
    int b    = i >> 10;
    int r    = i & 1023;
    const float* src = (half == 0) ? O1 : O2;
    out[(size_t)T_STEPS * BATCH * VOCAB + (size_t)half * 32768 + i] =
        src[(size_t)((T_STEPS - 1) * BATCH + b) * HID + 1024 + r];
}

extern "C" void kernel_launch(void* const* d_in, const int* in_sizes, int n_in,
                              void* d_out, int out_size)
{
    const int*   raw     = (const int*)  d_in[0];
    const float* h1y0    = (const float*)d_in[1];
    const float* h2y0    = (const float*)d_in[2];
    const float* enc     = (const float*)d_in[3];
    const float* snn_fc1 = (const float*)d_in[4];
    const float* snn_fc2 = (const float*)d_in[5];
    const float* rnn_fc1 = (const float*)d_in[6];
    const float* rnn_fc2 = (const float*)d_in[7];
    const float* rnn_fv1 = (const float*)d_in[8];
    const float* rnn_fv2 = (const float*)d_in[9];
    const float* dec_w   = (const float*)d_in[10];
    const float* dec_b   = (const float*)d_in[11];
    float* out = (float*)d_out;

    float *E, *CU1, *O1, *AU2, *O2, *W1f, *W2f;
    cudaGetSymbolAddress((void**)&E,   g_E);
    cudaGetSymbolAddress((void**)&CU1, g_CU1);
    cudaGetSymbolAddress((void**)&O1,  g_O1);
    cudaGetSymbolAddress((void**)&AU2, g_AU2);
    cudaGetSymbolAddress((void**)&O2,  g_O2);
    cudaGetSymbolAddress((void**)&W1f, g_W1f);
    cudaGetSymbolAddress((void**)&W2f, g_W2f);

    // 0) fuse projection weights on N (schedule-only; math unchanged)
    k_fusew<<<512, 256>>>(snn_fc1, rnn_fc1, W1f, NINP);
    k_fusew<<<512, 256>>>(snn_fc2, rnn_fc2, W2f, HID);

    // 1) gather embeddings
    k_gather<<<ROWS, 256>>>(raw, enc, E);

    // 2) layer-1 projections, ONE fused launch: CU1 = E @ [snn_fc1|rnn_fc1]
    dim3 gf(HID / 128, ROWS / 128);     // (16,16) = 256 CTAs
    sgemm_nn<false><<<gf, 256>>>(ROWS, HID, NINP, E, NINP, W1f, HID, CU1, HID);

    // 3) layer-1 spike scan (C1 = CU1 cols 0..1023)
    k_spike<<<128, 256>>>(CU1, HID, O1);

    // 4) layer-1 recurrent sigmoid chain (U1 = CU1 cols 1024..2047)
    for (int t = 0; t < T_STEPS; t++) {
        const float* xp = (t == 0) ? h1y0 : (O1 + (size_t)(t - 1) * BATCH * HID + 1024);
        int xs = (t == 0) ? 1024 : HID;
        k_rnn_step<<<64, 128>>>(CU1 + (size_t)t * BATCH * HID + 1024, HID,
                                xp, xs, rnn_fv1,
                                O1 + (size_t)t * BATCH * HID + 1024);
    }

    // 5) layer-2 projections, fused N: AU2 = O1 @ [snn_fc2|rnn_fc2]
    //    two kc=1024 panels (store, then __fadd_rn fold) — FROZEN association
    sgemm_nn<false><<<gf, 256>>>(ROWS, HID, 1024, O1, HID, W2f, HID, AU2, HID);
    sgemm_nn<true ><<<gf, 256>>>(ROWS, HID, 1024, O1 + 1024, HID,
                                 W2f + (size_t)1024 * HID, HID, AU2, HID);

    // 6) layer-2 spike scan (A2 = AU2 cols 0..1023)
    k_spike<<<128, 256>>>(AU2, HID, O2);

    // 7) layer-2 recurrent sigmoid chain (U2 = AU2 cols 1024..2047)
    for (int t = 0; t < T_STEPS; t++) {
        const float* xp = (t == 0) ? h2y0 : (O2 + (size_t)(t - 1) * BATCH * HID + 1024);
        int xs = (t == 0) ? 1024 : HID;
        k_rnn_step<<<64, 128>>>(AU2 + (size_t)t * BATCH * HID + 1024, HID,
                                xp, xs, rnn_fv2,
                                O2 + (size_t)t * BATCH * HID + 1024);
    }

    // 8) decoder — r13 TF32 kernel verbatim
    dim3 gd(VOCAB / 128, ROWS / 128);   // (250, 16)
    tf32_dec<<<gd, 256>>>(O2, dec_w, dec_b, out);

    // 9) final recurrent states into output tail
    k_tail<<<256, 256>>>(O1, O2, out);
}

// round 16
// speedup vs baseline: 2.0241x; 1.8455x over previous
#include <cuda_runtime.h>
#include <cuda_bf16.h>
#include <math.h>

#define T_STEPS 64
#define BATCH   32
#define NINP    1024
#define HID     2048
#define VOCAB   32000
#define ROWS    (T_STEPS*BATCH)
#define DECAYF  0.6f
#define THRESHF 0.6f

// Scratch (device globals; no runtime allocation allowed)
__device__ float g_E  [ROWS*NINP];      //  8 MB gathered embeddings
__device__ float g_CU1[ROWS*HID];       // 16 MB [C1 | U1] fused
__device__ float g_O1 [ROWS*HID];       // 16 MB [spike1 | h1_y]
__device__ float g_AU2[ROWS*HID];       // 16 MB [A2 | U2] fused
__device__ float g_O2 [ROWS*HID];       // 16 MB [spike2 | h2_y]
__device__ float g_W1f[NINP*HID];       //  8 MB [snn_fc1 | rnn_fc1]
__device__ float g_W2f[HID*HID];        // 16 MB [snn_fc2 | rnn_fc2]

// ---------------------------------------------------------------------------
// XLA fast-tanh with aarch64 LLVM FMA contraction (r12 recipe — FROZEN).
// ---------------------------------------------------------------------------
__device__ __forceinline__ float xla_tanh(float x) {
    const float a1  =  4.89352455891786e-03f;
    const float a3  =  6.37261928875436e-04f;
    const float a5  =  1.48572235717979e-05f;
    const float a7  =  5.12229709037114e-08f;
    const float a9  = -8.60467152213735e-11f;
    const float a11 =  2.00018790482477e-13f;
    const float a13 = -2.76076847742355e-16f;
    const float b0  =  4.89352518554385e-03f;
    const float b2  =  2.26843463243900e-03f;
    const float b4  =  1.18534705686654e-04f;
    const float b6  =  1.19825839466702e-06f;
    float xc = fminf(fmaxf(x, -9.0f), 9.0f);
    float x2 = __fmul_rn(xc, xc);
    float p  = __fmaf_rn(x2, a13, a11);
    p = __fmaf_rn(x2, p, a9);
    p = __fmaf_rn(x2, p, a7);
    p = __fmaf_rn(x2, p, a5);
    p = __fmaf_rn(x2, p, a3);
    p = __fmaf_rn(x2, p, a1);
    float num = __fmul_rn(xc, p);
    float q   = __fmaf_rn(x2, b6, b4);
    q = __fmaf_rn(x2, q, b2);
    q = __fmaf_rn(x2, q, b0);
    float t = __fdiv_rn(num, q);
    return (fabsf(x) < 0.0004f) ? x : t;
}

__device__ __forceinline__ float xla_sigmoid(float z) {
    float t = xla_tanh(__fmul_rn(0.5f, z));
    return __fmaf_rn(0.5f, t, 0.5f);
}

__device__ __forceinline__ unsigned f2tf32(float x) {
    unsigned r;
    asm("cvt.rna.tf32.f32 %0, %1;" : "=r"(r) : "f"(x));
    return r;
}

// Embedding gather
__global__ void k_gather(const int* __restrict__ idx,
                         const float* __restrict__ enc,
                         float* __restrict__ E)
{
    int row = blockIdx.x;
    int tok = idx[row];
    const float4* src = (const float4*)(enc + (size_t)tok * NINP);
    float4*       dst = (float4*)(E + (size_t)row * NINP);
    for (int i = threadIdx.x; i < NINP/4; i += blockDim.x) dst[i] = src[i];
}

// Fuse two [K,1024] weight matrices side-by-side into [K,2048]
__global__ void k_fusew(const float* __restrict__ A, const float* __restrict__ B,
                        float* __restrict__ D, int K)
{
    int i = blockIdx.x * blockDim.x + threadIdx.x;
    int n4 = K * 256;
    int stride = gridDim.x * blockDim.x;
    for (; i < n4; i += stride) {
        int row  = i >> 8;
        int col4 = (i & 255) * 4;
        *(float4*)(D + (size_t)row * HID + col4) =
            *(const float4*)(A + (size_t)row * 1024 + col4);
        *(float4*)(D + (size_t)row * HID + 1024 + col4) =
            *(const float4*)(B + (size_t)row * 1024 + col4);
    }
}

// ---------------------------------------------------------------------------
// Tiled fp32 SGEMM (NN), spike path — FROZEN per-element numerics
// (monolithic ascending __fmaf_rn chain; ACC folds the second kc=1024 panel
// with one __fadd_rn). BM=BN=128, BK=16, 256 threads, 8x8 microtile.
// ---------------------------------------------------------------------------
template<bool ACC>
__global__ void sgemm_nn(int M, int N, int K,
                         const float* __restrict__ A, int lda,
                         const float* __restrict__ B, int ldb,
                         float* __restrict__ C, int ldc)
{
    const int BK = 16;
    __shared__ float As[16][132];
    __shared__ float Bs[16][132];

    int tid = threadIdx.x;
    int tx  = tid & 15;
    int ty  = tid >> 4;
    int m0  = blockIdx.y * 128;
    int n0  = blockIdx.x * 128;

    float acc[8][8];
#pragma unroll
    for (int i = 0; i < 8; i++)
#pragma unroll
        for (int j = 0; j < 8; j++) acc[i][j] = 0.f;

    int a_r = tid >> 2;
    int a_k = (tid & 3) * 4;

    for (int kt = 0; kt < K; kt += BK) {
#pragma unroll
        for (int L = 0; L < 2; L++) {
            int m = a_r + L * 64;
            float4 v = *(const float4*)(A + (size_t)(m0 + m) * lda + kt + a_k);
            As[a_k + 0][m] = v.x;
            As[a_k + 1][m] = v.y;
            As[a_k + 2][m] = v.z;
            As[a_k + 3][m] = v.w;
        }
#pragma unroll
        for (int L = 0; L < 2; L++) {
            int k = (tid >> 5) + L * 8;
            int n = (tid & 31) * 4;
            float4 v = *(const float4*)(B + (size_t)(kt + k) * ldb + n0 + n);
            *(float4*)(&Bs[k][n]) = v;
        }
        __syncthreads();

#pragma unroll
        for (int k = 0; k < BK; k++) {
            float a[8], b[8];
            *(float4*)(a)     = *(const float4*)(&As[k][ty * 8]);
            *(float4*)(a + 4) = *(const float4*)(&As[k][ty * 8 + 4]);
            *(float4*)(b)     = *(const float4*)(&Bs[k][tx * 8]);
            *(float4*)(b + 4) = *(const float4*)(&Bs[k][tx * 8 + 4]);
#pragma unroll
            for (int i = 0; i < 8; i++)
#pragma unroll
                for (int j = 0; j < 8; j++)
                    acc[i][j] = __fmaf_rn(a[i], b[j], acc[i][j]);
        }
        __syncthreads();
    }

#pragma unroll
    for (int i = 0; i < 8; i++) {
        int m = m0 + ty * 8 + i;
        float* crow = C + (size_t)m * ldc + n0 + tx * 8;
        if (ACC) {
#pragma unroll
            for (int j = 0; j < 8; j++) crow[j] = __fadd_rn(crow[j], acc[i][j]);
        } else {
#pragma unroll
            for (int j = 0; j < 8; j++) crow[j] = acc[i][j];
        }
    }
}

// ---------------------------------------------------------------------------
// TF32 tensor-core decoder — r13 kernel body VERBATIM; grid axes swapped
// (m on blockIdx.x = fast) so each wave spans all m-tiles and dec_w streams
// from DRAM once instead of 16x. r14 verified the swap is bit-identical.
// ---------------------------------------------------------------------------
__global__ __launch_bounds__(256) void tf32_dec(
    const float* __restrict__ A,
    const float* __restrict__ B,
    const float* __restrict__ bias,
    float* __restrict__ C)
{
    __shared__ unsigned As[128][36];
    __shared__ unsigned Bs[128][36];

    int tid  = threadIdx.x;
    int wid  = tid >> 5;
    int lane = tid & 31;
    int gid  = lane >> 2;
    int tig  = lane & 3;
    int wm   = wid >> 2;
    int wn   = wid & 3;

    int m0 = blockIdx.x * 128;      // m fast
    int n0 = blockIdx.y * 128;      // n slow

    float c[4][4][4];
#pragma unroll
    for (int mf = 0; mf < 4; mf++)
#pragma unroll
        for (int nf = 0; nf < 4; nf++)
#pragma unroll
            for (int q = 0; q < 4; q++) c[mf][nf][q] = 0.f;

    int lr = tid >> 3;
    int lk = (tid & 7) * 4;

    for (int kt = 0; kt < HID; kt += 32) {
#pragma unroll
        for (int i = 0; i < 4; i++) {
            int row = lr + i * 32;
            float4 v = *(const float4*)(A + (size_t)(m0 + row) * HID + kt + lk);
            As[row][lk + 0] = f2tf32(v.x);
            As[row][lk + 1] = f2tf32(v.y);
            As[row][lk + 2] = f2tf32(v.z);
            As[row][lk + 3] = f2tf32(v.w);
        }
#pragma unroll
        for (int i = 0; i < 4; i++) {
            int row = lr + i * 32;
            float4 v = *(const float4*)(B + (size_t)(n0 + row) * HID + kt + lk);
            Bs[row][lk + 0] = f2tf32(v.x);
            Bs[row][lk + 1] = f2tf32(v.y);
            Bs[row][lk + 2] = f2tf32(v.z);
            Bs[row][lk + 3] = f2tf32(v.w);
        }
        __syncthreads();

#pragma unroll
        for (int ks = 0; ks < 4; ks++) {
            int k0 = ks * 8;
            unsigned a[4][4], b[4][2];
#pragma unroll
            for (int mf = 0; mf < 4; mf++) {
                int r = wm * 64 + mf * 16 + gid;
                a[mf][0] = As[r    ][k0 + tig];
                a[mf][1] = As[r + 8][k0 + tig];
                a[mf][2] = As[r    ][k0 + tig + 4];
                a[mf][3] = As[r + 8][k0 + tig + 4];
            }
#pragma unroll
            for (int nf = 0; nf < 4; nf++) {
                int cn = wn * 32 + nf * 8 + gid;
                b[nf][0] = Bs[cn][k0 + tig];
                b[nf][1] = Bs[cn][k0 + tig + 4];
            }
#pragma unroll
            for (int mf = 0; mf < 4; mf++)
#pragma unroll
                for (int nf = 0; nf < 4; nf++)
                    asm volatile(
                        "mma.sync.aligned.m16n8k8.row.col.f32.tf32.tf32.f32 "
                        "{%0,%1,%2,%3}, {%4,%5,%6,%7}, {%8,%9}, {%0,%1,%2,%3};"
                        : "+f"(c[mf][nf][0]), "+f"(c[mf][nf][1]),
                          "+f"(c[mf][nf][2]), "+f"(c[mf][nf][3])
                        : "r"(a[mf][0]), "r"(a[mf][1]), "r"(a[mf][2]), "r"(a[mf][3]),
                          "r"(b[nf][0]), "r"(b[nf][1]));
        }
        __syncthreads();
    }

#pragma unroll
    for (int mf = 0; mf < 4; mf++) {
        int r = m0 + wm * 64 + mf * 16 + gid;
#pragma unroll
        for (int nf = 0; nf < 4; nf++) {
            int cn = n0 + wn * 32 + nf * 8 + 2 * tig;
            float b0v = bias[cn], b1v = bias[cn + 1];
            C[(size_t)r * VOCAB + cn]           = c[mf][nf][0] + b0v;
            C[(size_t)r * VOCAB + cn + 1]       = c[mf][nf][1] + b1v;
            C[(size_t)(r + 8) * VOCAB + cn]     = c[mf][nf][2] + b0v;
            C[(size_t)(r + 8) * VOCAB + cn + 1] = c[mf][nf][3] + b1v;
        }
    }
}

// ---------------------------------------------------------------------------
// LIF membrane/spike scan — FROZEN arithmetic; Cm row stride parameterized.
// ---------------------------------------------------------------------------
__global__ void k_spike(const float* __restrict__ Cm, int cstride,
                        float* __restrict__ O)
{
    int gid = blockIdx.x * blockDim.x + threadIdx.x;
    int b = gid >> 10;
    int s = gid & 1023;
    float mem = 0.f, spk = 0.f;
    for (int t = 0; t < T_STEPS; t++) {
        float c = Cm[(size_t)(t * BATCH + b) * cstride + s];
        float m1 = __fmul_rn(mem, __fsub_rn(1.f, spk));
        mem = __fmaf_rn(m1, DECAYF, c);
        spk = (__fsub_rn(mem, THRESHF) > 0.f) ? 1.f : 0.f;
        O[((size_t)(t * BATCH + b) << 11) + s] = spk;
    }
}

// ---------------------------------------------------------------------------
// Recurrent step — r13 v1 VERBATIM (smem-staged W tile; proven ~11us/step)
// with ustride param added for fused [C|U] buffers (addressing only).
// Per-element chain: monolithic ascending FMA from zero, U added at end.
// ---------------------------------------------------------------------------
__global__ void k_rnn_step(const float* __restrict__ U, int ustride,
                           const float* __restrict__ Xp, int xstride,
                           const float* __restrict__ W,
                           float* __restrict__ Y)
{
    __shared__ float sx[32 * 33];
    __shared__ float sw[32 * 16];

    int tid = threadIdx.x;          // 0..127
    int b   = tid & 31;
    int jg  = tid >> 5;             // 0..3
    int jt  = blockIdx.x * 16;
    int j0  = jt + jg * 4;

    float acc[4] = {0.f, 0.f, 0.f, 0.f};

    for (int kc = 0; kc < 1024; kc += 32) {
#pragma unroll
        for (int p = 0; p < 8; p++) {
            int e  = tid + p * 128;
            int bl = e >> 5;
            int kl = e & 31;
            sx[kl * 33 + bl] = Xp[(size_t)bl * xstride + kc + kl];
        }
#pragma unroll
        for (int p = 0; p < 4; p++) {
            int e  = tid + p * 128;
            int kl = e >> 4;
            int jl = e & 15;
            sw[kl * 16 + jl] = W[(size_t)(kc + kl) * 1024 + jt + jl];
        }
        __syncthreads();
#pragma unroll
        for (int k = 0; k < 32; k++) {
            float xv = sx[k * 33 + b];
            const float* wr = &sw[k * 16 + jg * 4];
#pragma unroll
            for (int j = 0; j < 4; j++)
                acc[j] = __fmaf_rn(xv, wr[j], acc[j]);
        }
        __syncthreads();
    }

#pragma unroll
    for (int j = 0; j < 4; j++) {
        float z = __fadd_rn(U[(size_t)b * ustride + j0 + j], acc[j]);
        Y[(size_t)b * HID + j0 + j] = xla_sigmoid(z);
    }
}

// Copy final h1_y / h2_y states into the tail of d_out.
__global__ void k_tail(const float* __restrict__ O1,
                       const float* __restrict__ O2,
                       float* __restrict__ out)
{
    int gid  = blockIdx.x * blockDim.x + threadIdx.x;
    int half = gid >> 15;
    int i    = gid & 32767;
    int b    = i >> 10;
    int r    = i & 1023;
    const float* src = (half == 0) ? O1 : O2;
    out[(size_t)T_STEPS * BATCH * VOCAB + (size_t)half * 32768 + i] =
        src[(size_t)((T_STEPS - 1) * BATCH + b) * HID + 1024 + r];
}

extern "C" void kernel_launch(void* const* d_in, const int* in_sizes, int n_in,
                              void* d_out, int out_size)
{
    const int*   raw     = (const int*)  d_in[0];
    const float* h1y0    = (const float*)d_in[1];
    const float* h2y0    = (const float*)d_in[2];
    const float* enc     = (const float*)d_in[3];
    const float* snn_fc1 = (const float*)d_in[4];
    const float* snn_fc2 = (const float*)d_in[5];
    const float* rnn_fc1 = (const float*)d_in[6];
    const float* rnn_fc2 = (const float*)d_in[7];
    const float* rnn_fv1 = (const float*)d_in[8];
    const float* rnn_fv2 = (const float*)d_in[9];
    const float* dec_w   = (const float*)d_in[10];
    const float* dec_b   = (const float*)d_in[11];
    float* out = (float*)d_out;

    float *E, *CU1, *O1, *AU2, *O2, *W1f, *W2f;
    cudaGetSymbolAddress((void**)&E,   g_E);
    cudaGetSymbolAddress((void**)&CU1, g_CU1);
    cudaGetSymbolAddress((void**)&O1,  g_O1);
    cudaGetSymbolAddress((void**)&AU2, g_AU2);
    cudaGetSymbolAddress((void**)&O2,  g_O2);
    cudaGetSymbolAddress((void**)&W1f, g_W1f);
    cudaGetSymbolAddress((void**)&W2f, g_W2f);

    // 0) fuse projection weights on N (schedule-only; math unchanged)
    k_fusew<<<512, 256>>>(snn_fc1, rnn_fc1, W1f, NINP);
    k_fusew<<<512, 256>>>(snn_fc2, rnn_fc2, W2f, HID);

    // 1) gather embeddings
    k_gather<<<ROWS, 256>>>(raw, enc, E);

    // 2) layer-1 projections, ONE fused launch: CU1 = E @ [snn_fc1|rnn_fc1]
    dim3 gf(HID / 128, ROWS / 128);     // (16,16) = 256 CTAs
    sgemm_nn<false><<<gf, 256>>>(ROWS, HID, NINP, E, NINP, W1f, HID, CU1, HID);

    // 3) layer-1 spike scan (C1 = CU1 cols 0..1023)
    k_spike<<<128, 256>>>(CU1, HID, O1);

    // 4) layer-1 recurrent sigmoid chain (U1 = CU1 cols 1024..2047)
    for (int t = 0; t < T_STEPS; t++) {
        const float* xp = (t == 0) ? h1y0 : (O1 + (size_t)(t - 1) * BATCH * HID + 1024);
        int xs = (t == 0) ? 1024 : HID;
        k_rnn_step<<<64, 128>>>(CU1 + (size_t)t * BATCH * HID + 1024, HID,
                                xp, xs, rnn_fv1,
                                O1 + (size_t)t * BATCH * HID + 1024);
    }

    // 5) layer-2 projections, fused N: AU2 = O1 @ [snn_fc2|rnn_fc2]
    //    two kc=1024 panels (store, then __fadd_rn fold) — FROZEN association
    sgemm_nn<false><<<gf, 256>>>(ROWS, HID, 1024, O1, HID, W2f, HID, AU2, HID);
    sgemm_nn<true ><<<gf, 256>>>(ROWS, HID, 1024, O1 + 1024, HID,
                                 W2f + (size_t)1024 * HID, HID, AU2, HID);

    // 6) layer-2 spike scan (A2 = AU2 cols 0..1023)
    k_spike<<<128, 256>>>(AU2, HID, O2);

    // 7) layer-2 recurrent sigmoid chain (U2 = AU2 cols 1024..2047)
    for (int t = 0; t < T_STEPS; t++) {
        const float* xp = (t == 0) ? h2y0 : (O2 + (size_t)(t - 1) * BATCH * HID + 1024);
        int xs = (t == 0) ? 1024 : HID;
        k_rnn_step<<<64, 128>>>(AU2 + (size_t)t * BATCH * HID + 1024, HID,
                                xp, xs, rnn_fv2,
                                O2 + (size_t)t * BATCH * HID + 1024);
    }

    // 8) decoder — r13 TF32 kernel, m-fast grid (dec_w single DRAM pass)
    dim3 gd(ROWS / 128, VOCAB / 128);   // (16, 250): m fast, n slow
    tf32_dec<<<gd, 256>>>(O2, dec_w, dec_b, out);

    // 9) final recurrent states into output tail
    k_tail<<<256, 256>>>(O1, O2, out);
}